// round 4
// baseline (speedup 1.0000x reference)
#include <cuda_runtime.h>
#include <cuda_fp16.h>

#define NN 16
#define VV 5023
#define FF 9976
#define HH 512
#define WW 512
#define NV (NN * VV)            // 80368
#define NF (NN * FF)            // 159616
#define NPIX (NN * HH * WW)     // 4194304
#define MMBLK 40                // minmax partial blocks

__device__ float g_pmn[MMBLK];
__device__ float g_pmx[MMBLK];
// 8B per (image,face): z0 (fp32) + (z1-z0, z2-z0) packed fp16x2
__device__ float2 g_fz8[NF];

// ---------------------------------------------------------------------------
// Kernel 1: partial min/max of tv[:,:,2]. Plain stores -> no init kernel.
__global__ void __launch_bounds__(1024) minmax_partial_kernel(const float* __restrict__ tv) {
    int i = blockIdx.x * blockDim.x + threadIdx.x;
    float z0 = tv[2];
    float mn = z0, mx = z0;
    for (int k = i; k < NV; k += MMBLK * 1024) {
        float z = tv[3 * k + 2];
        mn = fminf(mn, z);
        mx = fmaxf(mx, z);
    }
    #pragma unroll
    for (int o = 16; o > 0; o >>= 1) {
        mn = fminf(mn, __shfl_xor_sync(0xFFFFFFFFu, mn, o));
        mx = fmaxf(mx, __shfl_xor_sync(0xFFFFFFFFu, mx, o));
    }
    __shared__ float smn[32], smx[32];
    int lane = threadIdx.x & 31, w = threadIdx.x >> 5;
    if (lane == 0) { smn[w] = mn; smx[w] = mx; }
    __syncthreads();
    if (threadIdx.x == 0) {
        float bmn = smn[0], bmx = smx[0];
        for (int k = 1; k < 32; k++) {
            bmn = fminf(bmn, smn[k]);
            bmx = fmaxf(bmx, smx[k]);
        }
        g_pmn[blockIdx.x] = bmn;
        g_pmx[blockIdx.x] = bmx;
    }
}

// ---------------------------------------------------------------------------
// Kernel 2: build per-(image,face) table. Each block first reduces the 40
// partials (cheap, L2-hit), then computes its faces.
__global__ void __launch_bounds__(256) facez_kernel(const float* __restrict__ tv,
                                                    const int* __restrict__ faces) {
    __shared__ float s_m, s_R;
    if (threadIdx.x == 0) {
        float m = g_pmn[0], M = g_pmx[0];
        #pragma unroll
        for (int k = 1; k < MMBLK; k++) {
            m = fminf(m, g_pmn[k]);
            M = fmaxf(M, g_pmx[k]);
        }
        s_m = m;
        s_R = M - m;
    }
    __syncthreads();
    int t = blockIdx.x * blockDim.x + threadIdx.x;
    if (t >= NF) return;
    float m = s_m, R = s_R;
    int n = t / FF;
    int f = t - n * FF;
    int v0 = __ldg(faces + 3 * f);
    int v1 = __ldg(faces + 3 * f + 1);
    int v2 = __ldg(faces + 3 * f + 2);
    long long vb = (long long)n * VV;
    // reference rounding: zn = (R - fl(z - m)) / R with R = fl(M - m)
    float zn0 = (R - (tv[3 * (vb + v0) + 2] - m)) / R;
    float zn1 = (R - (tv[3 * (vb + v1) + 2] - m)) / R;
    float zn2 = (R - (tv[3 * (vb + v2) + 2] - m)) / R;
    __half2 d = __floats2half2_rn(zn1 - zn0, zn2 - zn0);
    float2 e;
    e.x = zn0;
    e.y = __uint_as_float(*reinterpret_cast<unsigned int*>(&d));
    g_fz8[t] = e;
}

// ---------------------------------------------------------------------------
// Kernel 3: pixel interpolation. 8 px/thread; gathers (8B, L1-cached) issued
// before the streaming loads; streaming uses evict-first (.cs) so it doesn't
// evict the 1.25MB gather table from L1.
__global__ void __launch_bounds__(256, 4) pixel_kernel(
    const float* __restrict__ bary,
    const int* __restrict__ p2f,
    float* __restrict__ out)
{
    int t = blockIdx.x * blockDim.x + threadIdx.x;
    long long base = (long long)t * 8;
    if (base >= NPIX) return;

    int4 pa = __ldcs(reinterpret_cast<const int4*>(p2f + base));
    int4 pb = __ldcs(reinterpret_cast<const int4*>(p2f + base) + 1);
    int ps[8] = {pa.x, pa.y, pa.z, pa.w, pb.x, pb.y, pb.z, pb.w};

    // Issue all 8 scattered gathers first (deep in the LSU queue early).
    float2 e[8];
    #pragma unroll
    for (int i = 0; i < 8; i++) {
        int pc = ps[i] >= 0 ? ps[i] : 0;
        e[i] = __ldg(&g_fz8[pc]);
    }

    // 24 streaming bary floats.
    const float4* bp = reinterpret_cast<const float4*>(bary + base * 3);
    float w[24];
    #pragma unroll
    for (int q = 0; q < 6; q++) {
        float4 v = __ldcs(bp + q);
        w[4 * q + 0] = v.x;
        w[4 * q + 1] = v.y;
        w[4 * q + 2] = v.z;
        w[4 * q + 3] = v.w;
    }

    float res[8];
    #pragma unroll
    for (int i = 0; i < 8; i++) {
        float b0 = w[3 * i], b1 = w[3 * i + 1], b2 = w[3 * i + 2];
        unsigned int db = __float_as_uint(e[i].y);
        __half2 dh = *reinterpret_cast<__half2*>(&db);
        float2 d = __half22float2(dh);
        float s = e[i].x * (b0 + b1 + b2) + b1 * d.x + b2 * d.y;
        res[i] = ps[i] >= 0 ? s : 0.0f;
    }

    float4* op = reinterpret_cast<float4*>(out + base);
    __stcs(op, make_float4(res[0], res[1], res[2], res[3]));
    __stcs(op + 1, make_float4(res[4], res[5], res[6], res[7]));
}

extern "C" void kernel_launch(void* const* d_in, const int* in_sizes, int n_in,
                              void* d_out, int out_size) {
    const float* tv = nullptr;      // 241104
    const float* bary = nullptr;    // 12582912
    const int* faces = nullptr;     // 29928
    const int* p2f = nullptr;       // 4194304
    for (int i = 0; i < n_in; i++) {
        switch (in_sizes[i]) {
            case NN * VV * 3:            tv    = (const float*)d_in[i]; break;
            case NN * HH * WW * 3:       bary  = (const float*)d_in[i]; break;
            case FF * 3:                 faces = (const int*)d_in[i];   break;
            case NN * HH * WW:           p2f   = (const int*)d_in[i];   break;
        }
    }
    float* out = (float*)d_out;

    minmax_partial_kernel<<<MMBLK, 1024>>>(tv);
    facez_kernel<<<(NF + 255) / 256, 256>>>(tv, faces);
    pixel_kernel<<<(NPIX / 8 + 255) / 256, 256>>>(bary, p2f, out);
}